// round 7
// baseline (speedup 1.0000x reference)
#include <cuda_runtime.h>
#include <cuda_fp16.h>
#include <cstdint>

#define NMAX 100000
#define EMAXN 1600000
#define KF 256
#define HD 128

// ---------------- scratch (device globals; no allocs allowed) ----------------
__device__ __half g_fth[(size_t)NMAX * HD]; // projected features fp16 [N,128]
__device__ float g_el[NMAX * 4];            // left logits  [N,4]
__device__ float g_er[NMAX * 4];            // right logits [N,4]
__device__ float g_a[(size_t)EMAXN * 4];    // per-edge exp coefficients, CSR order
__device__ int   g_cnt[NMAX];               // histogram
__device__ int   g_off[NMAX + 1];           // CSR offsets (destructively shifted by scatter)
__device__ int   g_bsum[512];               // block partial sums
__device__ int   g_boff[512];               // block exclusive prefixes
__device__ int   g_esrc[EMAXN];             // src ids bucketed by dst
__device__ int            g_arrive1, g_arrive2;
__device__ volatile int   g_flag1, g_flag2;

// ================= tf32 tensor-core GEMM (4-stage cp.async pipeline) =========
// ft = feat[M,256] @ fc_w[128,256]^T ; fused el/er ; fp16 ft output.
// Block tile 128x128, BK=16, 4-stage pipeline, 8 warps (2m x 4n), warp 64x32.
#define BK      16
#define SMS     20                 // 16 + 4 pad floats per row
#define STAGEF  (128 * SMS)        // floats per stage per array
#define NSTAGE  4
#define GEMM_SMEM_BYTES (2 * NSTAGE * STAGEF * 4)

__device__ __forceinline__ unsigned f2tf32(float f) {
    unsigned r;
    asm("cvt.rna.tf32.f32 %0, %1;" : "=r"(r) : "f"(f));
    return r;
}

__device__ __forceinline__ void cp16(unsigned int s, const float* g, bool pred) {
    int sz = pred ? 16 : 0;
    asm volatile("cp.async.ca.shared.global [%0], [%1], 16, %2;\n"
                 :: "r"(s), "l"(g), "r"(sz));
}

__global__ __launch_bounds__(256) void mma_gemm_kernel(const float* __restrict__ A,
                                                       const float* __restrict__ B,
                                                       const float* __restrict__ attn_l,
                                                       const float* __restrict__ attn_r,
                                                       int M) {
    extern __shared__ float smem_dyn[];
    float* As = smem_dyn;                       // NSTAGE * STAGEF
    float* Bs = smem_dyn + NSTAGE * STAGEF;     // NSTAGE * STAGEF

    const int tid    = threadIdx.x;
    const int wid    = tid >> 5;
    const int lane   = tid & 31;
    const int warp_m = wid >> 2;      // 0..1
    const int warp_n = wid & 3;       // 0..3 (head)
    const int g      = lane >> 2;     // 0..7
    const int tg     = lane & 3;      // 0..3

    const int row0 = blockIdx.x * 128;
    const int lr   = tid >> 2;        // 0..63
    const int lc   = (tid & 3) * 4;   // 0,4,8,12

    float c[4][4][4];
#pragma unroll
    for (int i = 0; i < 4; i++)
#pragma unroll
        for (int j = 0; j < 4; j++)
#pragma unroll
            for (int k = 0; k < 4; k++) c[i][j][k] = 0.f;

    const int  ar0 = row0 + lr, ar1 = row0 + lr + 64;
    const bool ok0 = (ar0 < M), ok1 = (ar1 < M);
    const float* pa0 = A + (size_t)(ok0 ? ar0 : 0) * KF + lc;
    const float* pa1 = A + (size_t)(ok1 ? ar1 : 0) * KF + lc;
    const float* pb0 = B + (size_t)lr * KF + lc;
    const float* pb1 = B + (size_t)(lr + 64) * KF + lc;

    unsigned int sa0 = (unsigned int)__cvta_generic_to_shared(&As[lr * SMS + lc]);
    unsigned int sa1 = (unsigned int)__cvta_generic_to_shared(&As[(lr + 64) * SMS + lc]);
    unsigned int sb0 = (unsigned int)__cvta_generic_to_shared(&Bs[lr * SMS + lc]);
    unsigned int sb1 = (unsigned int)__cvta_generic_to_shared(&Bs[(lr + 64) * SMS + lc]);
    const unsigned int stagebytes = STAGEF * 4;

    const int NT = KF / BK;   // 16

    // prologue: stage tiles 0..2
#pragma unroll
    for (int s = 0; s < NSTAGE - 1; s++) {
        unsigned int o = s * stagebytes;
        int kt = s * BK;
        cp16(sa0 + o, pa0 + kt, ok0); cp16(sa1 + o, pa1 + kt, ok1);
        cp16(sb0 + o, pb0 + kt, true); cp16(sb1 + o, pb1 + kt, true);
        asm volatile("cp.async.commit_group;\n");
    }

#pragma unroll 1
    for (int t = 0; t < NT; t++) {
        // wait until group t is complete
        if (t + 2 < NT)      asm volatile("cp.async.wait_group 2;\n");
        else if (t + 1 < NT) asm volatile("cp.async.wait_group 1;\n");
        else                 asm volatile("cp.async.wait_group 0;\n");
        __syncthreads();   // data of tile t visible; all warps done reading slot (t+3)&3

        if (t + NSTAGE - 1 < NT) {
            int s = (t + NSTAGE - 1) & (NSTAGE - 1);
            unsigned int o = s * stagebytes;
            int kt = (t + NSTAGE - 1) * BK;
            cp16(sa0 + o, pa0 + kt, ok0); cp16(sa1 + o, pa1 + kt, ok1);
            cp16(sb0 + o, pb0 + kt, true); cp16(sb1 + o, pb1 + kt, true);
            asm volatile("cp.async.commit_group;\n");
        }

        const float* Ab = As + (t & (NSTAGE - 1)) * STAGEF;
        const float* Bb = Bs + (t & (NSTAGE - 1)) * STAGEF;
#pragma unroll
        for (int k8 = 0; k8 < BK; k8 += 8) {
            unsigned a[4][4], b[4][2];
#pragma unroll
            for (int mt = 0; mt < 4; mt++) {
                int mb = warp_m * 64 + mt * 16;
                a[mt][0] = f2tf32(Ab[(mb + g)     * SMS + k8 + tg]);
                a[mt][1] = f2tf32(Ab[(mb + g + 8) * SMS + k8 + tg]);
                a[mt][2] = f2tf32(Ab[(mb + g)     * SMS + k8 + tg + 4]);
                a[mt][3] = f2tf32(Ab[(mb + g + 8) * SMS + k8 + tg + 4]);
            }
#pragma unroll
            for (int nt = 0; nt < 4; nt++) {
                int nb = warp_n * 32 + nt * 8;
                b[nt][0] = f2tf32(Bb[(nb + g) * SMS + k8 + tg]);
                b[nt][1] = f2tf32(Bb[(nb + g) * SMS + k8 + tg + 4]);
            }
#pragma unroll
            for (int mt = 0; mt < 4; mt++)
#pragma unroll
                for (int nt = 0; nt < 4; nt++) {
                    asm volatile(
                        "mma.sync.aligned.m16n8k8.row.col.f32.tf32.tf32.f32 "
                        "{%0,%1,%2,%3}, {%4,%5,%6,%7}, {%8,%9}, {%0,%1,%2,%3};\n"
                        : "+f"(c[mt][nt][0]), "+f"(c[mt][nt][1]),
                          "+f"(c[mt][nt][2]), "+f"(c[mt][nt][3])
                        : "r"(a[mt][0]), "r"(a[mt][1]), "r"(a[mt][2]), "r"(a[mt][3]),
                          "r"(b[nt][0]), "r"(b[nt][1]));
                }
        }
    }

    // ---- attn weights for this thread's 8 columns (within head warp_n) ----
    float wl[4][2], wr[4][2];
#pragma unroll
    for (int nt = 0; nt < 4; nt++) {
        int col = warp_n * 32 + nt * 8 + 2 * tg;
        wl[nt][0] = attn_l[col]; wl[nt][1] = attn_l[col + 1];
        wr[nt][0] = attn_r[col]; wr[nt][1] = attn_r[col + 1];
    }

    // ---- epilogue: fp16 ft stores + fused el/er ----
#pragma unroll
    for (int mt = 0; mt < 4; mt++) {
        int r0 = row0 + warp_m * 64 + mt * 16 + g;

        float el0 = 0.f, er0 = 0.f, el1 = 0.f, er1 = 0.f;
#pragma unroll
        for (int nt = 0; nt < 4; nt++) {
            el0 = fmaf(c[mt][nt][0], wl[nt][0], el0); el0 = fmaf(c[mt][nt][1], wl[nt][1], el0);
            er0 = fmaf(c[mt][nt][0], wr[nt][0], er0); er0 = fmaf(c[mt][nt][1], wr[nt][1], er0);
            el1 = fmaf(c[mt][nt][2], wl[nt][0], el1); el1 = fmaf(c[mt][nt][3], wl[nt][1], el1);
            er1 = fmaf(c[mt][nt][2], wr[nt][0], er1); er1 = fmaf(c[mt][nt][3], wr[nt][1], er1);
        }
        el0 += __shfl_xor_sync(0xffffffffu, el0, 1); el0 += __shfl_xor_sync(0xffffffffu, el0, 2);
        er0 += __shfl_xor_sync(0xffffffffu, er0, 1); er0 += __shfl_xor_sync(0xffffffffu, er0, 2);
        el1 += __shfl_xor_sync(0xffffffffu, el1, 1); el1 += __shfl_xor_sync(0xffffffffu, el1, 2);
        er1 += __shfl_xor_sync(0xffffffffu, er1, 1); er1 += __shfl_xor_sync(0xffffffffu, er1, 2);

#pragma unroll
        for (int nt = 0; nt < 4; nt++) {
            int col = warp_n * 32 + nt * 8 + 2 * tg;
            if (r0 < M)
                *(__half2*)&g_fth[(size_t)r0 * HD + col] =
                    __floats2half2_rn(c[mt][nt][0], c[mt][nt][1]);
            if (r0 + 8 < M)
                *(__half2*)&g_fth[(size_t)(r0 + 8) * HD + col] =
                    __floats2half2_rn(c[mt][nt][2], c[mt][nt][3]);
        }
        if (tg == 0) {
            if (r0 < M)     { g_el[r0 * 4 + warp_n] = el0;       g_er[r0 * 4 + warp_n] = er0; }
            if (r0 + 8 < M) { g_el[(r0 + 8) * 4 + warp_n] = el1; g_er[(r0 + 8) * 4 + warp_n] = er1; }
        }
    }
}

// ================= histogram (+ reset of sync state) =========================
__global__ void hist_kernel(const int* __restrict__ dst, int E) {
    if (blockIdx.x == 0 && threadIdx.x == 0) {
        g_arrive1 = 0; g_arrive2 = 0; g_flag1 = 0; g_flag2 = 0;
    }
    int e = blockIdx.x * blockDim.x + threadIdx.x;
    if (e < E) atomicAdd(&g_cnt[dst[e]], 1);
}

// ================= fused scan + scatter (single kernel, grid barriers) =======
// Scatter also precomputes per-edge exp coefficients (all 4 heads) so the
// aggregate never touches logits/exp.
__global__ __launch_bounds__(256) void scan_scatter_kernel(const int* __restrict__ src,
                                                           const int* __restrict__ dst,
                                                           int M, int E, int nblk) {
    __shared__ int sh[256];
    __shared__ int sh2[512];
    __shared__ int s_last;

    const int b = blockIdx.x, t = threadIdx.x;
    const int i = b * 256 + t;

    // ---- in-block inclusive scan of counts ----
    int v = (i < M) ? g_cnt[i] : 0;
    sh[t] = v;
    __syncthreads();
#pragma unroll
    for (int ofs = 1; ofs < 256; ofs <<= 1) {
        int u = (t >= ofs) ? sh[t - ofs] : 0;
        __syncthreads();
        sh[t] += u;
        __syncthreads();
    }
    if (t == 255) g_bsum[b] = sh[255];
    __threadfence();
    __syncthreads();

    // ---- grid barrier 1: last-arriving block scans the partials ----
    if (t == 0) {
        int tk = atomicAdd(&g_arrive1, 1);
        s_last = (tk == nblk - 1) ? 1 : 0;
    }
    __syncthreads();
    if (s_last) {
        int e0 = (t < nblk) ? g_bsum[t] : 0;
        int e1 = (t + 256 < nblk) ? g_bsum[t + 256] : 0;
        sh2[t] = e0; sh2[t + 256] = e1;
        __syncthreads();
#pragma unroll
        for (int ofs = 1; ofs < 512; ofs <<= 1) {
            int u0 = (t >= ofs) ? sh2[t - ofs] : 0;
            int u1 = (t + 256 >= ofs) ? sh2[t + 256 - ofs] : 0;
            __syncthreads();
            sh2[t] += u0; sh2[t + 256] += u1;
            __syncthreads();
        }
        g_boff[t] = sh2[t] - e0;               // exclusive
        g_boff[t + 256] = sh2[t + 256] - e1;
        __threadfence();
        __syncthreads();
        if (t == 0) g_flag1 = 1;
    } else {
        if (t == 0) { while (g_flag1 == 0) {} }
        __syncthreads();
    }
    __threadfence();

    // ---- write global offsets ----
    int prefix = g_boff[b];
    if (i < M) g_off[i + 1] = sh[t] + prefix;
    if (i == 0) g_off[0] = 0;
    __threadfence();
    __syncthreads();

    // ---- grid barrier 2: all offsets visible before scatter ----
    if (t == 0) {
        int tk = atomicAdd(&g_arrive2, 1);
        if (tk == nblk - 1) { __threadfence(); g_flag2 = 1; }
        else { while (g_flag2 == 0) {} }
    }
    __syncthreads();
    __threadfence();

    // ---- destructive scatter + per-edge exp coefficients ----
    const int stride = nblk * 256;
    for (int e = i; e < E; e += stride) {
        int s = src[e], d = dst[e];
        int pos = atomicAdd(&g_off[d], 1);
        g_esrc[pos] = s;
        float4 el4 = *(const float4*)&g_el[s * 4];
        float4 er4 = *(const float4*)&g_er[d * 4];
        float w; float4 a4;
        w = el4.x + er4.x; w = w > 0.f ? w : 0.2f * w; a4.x = __expf(w);
        w = el4.y + er4.y; w = w > 0.f ? w : 0.2f * w; a4.y = __expf(w);
        w = el4.z + er4.z; w = w > 0.f ? w : 0.2f * w; a4.z = __expf(w);
        w = el4.w + er4.w; w = w > 0.f ? w : 0.2f * w; a4.w = __expf(w);
        *(float4*)&g_a[(size_t)pos * 4] = a4;
    }
}

// ================= fused softmax + aggregate (warp per dst node) =============
// Coefficients precomputed; per edge per warp: 1 LDG a + 1 LDG.64 ft + cvt+FMA.
__global__ __launch_bounds__(256) void aggregate_kernel(float* __restrict__ out, int N) {
    int d    = (blockIdx.x * blockDim.x + threadIdx.x) >> 5;
    int lane = threadIdx.x & 31;
    if (d >= N) return;

    int beg = (d == 0) ? 0 : g_off[d - 1];
    int end = g_off[d];
    const int h = lane >> 3;
    const __half* fb = g_fth + lane * 4;

    float4 acc = make_float4(0.f, 0.f, 0.f, 0.f);
    float  asum = 0.f;

    auto one = [&](int p_) {
        int   s = g_esrc[p_];
        float a = g_a[(size_t)p_ * 4 + h];
        asum += a;
        uint2 raw = *(const uint2*)(fb + ((size_t)s << 7));
        float2 f0 = __half22float2(*(__half2*)&raw.x);
        float2 f1 = __half22float2(*(__half2*)&raw.y);
        acc.x = fmaf(a, f0.x, acc.x); acc.y = fmaf(a, f0.y, acc.y);
        acc.z = fmaf(a, f1.x, acc.z); acc.w = fmaf(a, f1.y, acc.w);
    };

    int p = beg;
    for (; p < end && (p & 3); ++p) one(p);          // align to int4
    for (; p + 4 <= end; p += 4) {
        int4 s4 = *(const int4*)&g_esrc[p];
        float a0 = g_a[(size_t)p * 4 + h];
        float a1 = g_a[(size_t)(p + 1) * 4 + h];
        float a2 = g_a[(size_t)(p + 2) * 4 + h];
        float a3 = g_a[(size_t)(p + 3) * 4 + h];
        uint2 r0 = *(const uint2*)(fb + ((size_t)s4.x << 7));
        uint2 r1 = *(const uint2*)(fb + ((size_t)s4.y << 7));
        uint2 r2 = *(const uint2*)(fb + ((size_t)s4.z << 7));
        uint2 r3 = *(const uint2*)(fb + ((size_t)s4.w << 7));
        asum += (a0 + a1) + (a2 + a3);
        float2 f;
        f = __half22float2(*(__half2*)&r0.x); acc.x = fmaf(a0, f.x, acc.x); acc.y = fmaf(a0, f.y, acc.y);
        f = __half22float2(*(__half2*)&r0.y); acc.z = fmaf(a0, f.x, acc.z); acc.w = fmaf(a0, f.y, acc.w);
        f = __half22float2(*(__half2*)&r1.x); acc.x = fmaf(a1, f.x, acc.x); acc.y = fmaf(a1, f.y, acc.y);
        f = __half22float2(*(__half2*)&r1.y); acc.z = fmaf(a1, f.x, acc.z); acc.w = fmaf(a1, f.y, acc.w);
        f = __half22float2(*(__half2*)&r2.x); acc.x = fmaf(a2, f.x, acc.x); acc.y = fmaf(a2, f.y, acc.y);
        f = __half22float2(*(__half2*)&r2.y); acc.z = fmaf(a2, f.x, acc.z); acc.w = fmaf(a2, f.y, acc.w);
        f = __half22float2(*(__half2*)&r3.x); acc.x = fmaf(a3, f.x, acc.x); acc.y = fmaf(a3, f.y, acc.y);
        f = __half22float2(*(__half2*)&r3.y); acc.z = fmaf(a3, f.x, acc.z); acc.w = fmaf(a3, f.y, acc.w);
    }
    for (; p < end; ++p) one(p);

    float inv = (asum > 0.f) ? (1.f / asum) : 0.f;
    acc.x *= inv; acc.y *= inv; acc.z *= inv; acc.w *= inv;
    *(float4*)&out[(size_t)d * HD + lane * 4] = acc;
}

// ================= launch ====================================================
extern "C" void kernel_launch(void* const* d_in, const int* in_sizes, int n_in,
                              void* d_out, int out_size) {
    const float* feat   = (const float*)d_in[0];
    const float* fc_w   = (const float*)d_in[1];
    const float* attn_l = (const float*)d_in[2];
    const float* attn_r = (const float*)d_in[3];
    const int*   src    = (const int*)d_in[4];
    const int*   dst    = (const int*)d_in[5];
    float*       out    = (float*)d_out;

    int M = in_sizes[0] / KF;   // nodes
    int E = in_sizes[4];        // edges
    int nblk = (M + 255) / 256;

    void* cnt_ptr = nullptr;
    cudaGetSymbolAddress(&cnt_ptr, g_cnt);
    cudaMemsetAsync(cnt_ptr, 0, (size_t)M * sizeof(int), 0);

    // projection (tf32 MMA, 4-stage cp.async) + fused logits + fp16 ft
    cudaFuncSetAttribute(mma_gemm_kernel,
                         cudaFuncAttributeMaxDynamicSharedMemorySize, GEMM_SMEM_BYTES);
    mma_gemm_kernel<<<(M + 127) / 128, 256, GEMM_SMEM_BYTES>>>(feat, fc_w, attn_l, attn_r, M);

    // CSR build: histogram, then fused scan+scatter (+ exp coefficients)
    hist_kernel<<<(E + 255) / 256, 256>>>(dst, E);
    scan_scatter_kernel<<<nblk, 256>>>(src, dst, M, E, nblk);

    // fused softmax + aggregation, one warp per dst node
    aggregate_kernel<<<(M * 32 + 255) / 256, 256>>>(out, M);
}

// round 8
// speedup vs baseline: 1.6046x; 1.6046x over previous
#include <cuda_runtime.h>
#include <cuda_fp16.h>
#include <cstdint>

#define NMAX 100000
#define EMAXN 1600000
#define KF 256
#define HD 128

// ---------------- scratch (device globals; no allocs allowed) ----------------
__device__ float g_ft[(size_t)NMAX * HD];   // projected features fp32 [N,128]
__device__ float g_el[NMAX * 4];            // left logits  [N,4]
__device__ float g_er[NMAX * 4];            // right logits [N,4]
__device__ int   g_cnt[NMAX];               // histogram
__device__ int   g_off[NMAX + 1];           // CSR offsets (destructively shifted by scatter)
__device__ int   g_bsum[512];               // block partial sums
__device__ int   g_boff[512];               // block exclusive prefixes
__device__ int   g_esrc[EMAXN];             // src ids bucketed by dst
__device__ int            g_arrive1, g_arrive2;
__device__ volatile int   g_flag1, g_flag2;

// ================= tf32 tensor-core GEMM (cp.async double-buffered) ==========
// ft = feat[M,256] @ fc_w[128,256]^T ; fused el/er ; fp32 ft output.
// Block tile 128x128, BK=16, 2-stage pipeline, 8 warps (2m x 4n), warp 64x32.
#define BK   16
#define SMS  20   // 16 + 4 pad floats per row

__device__ __forceinline__ unsigned f2tf32(float f) {
    unsigned r;
    asm("cvt.rna.tf32.f32 %0, %1;" : "=r"(r) : "f"(f));
    return r;
}

__device__ __forceinline__ void cp16(unsigned int s, const float* g, bool pred) {
    int sz = pred ? 16 : 0;
    asm volatile("cp.async.ca.shared.global [%0], [%1], 16, %2;\n"
                 :: "r"(s), "l"(g), "r"(sz));
}

__global__ __launch_bounds__(256) void mma_gemm_kernel(const float* __restrict__ A,
                                                       const float* __restrict__ B,
                                                       const float* __restrict__ attn_l,
                                                       const float* __restrict__ attn_r,
                                                       int M) {
    __shared__ float As[2][128 * SMS];
    __shared__ float Bs[2][128 * SMS];

    const int tid    = threadIdx.x;
    const int wid    = tid >> 5;
    const int lane   = tid & 31;
    const int warp_m = wid >> 2;      // 0..1
    const int warp_n = wid & 3;       // 0..3 (head)
    const int g      = lane >> 2;     // 0..7
    const int tg     = lane & 3;      // 0..3

    const int row0 = blockIdx.x * 128;
    const int lr   = tid >> 2;        // 0..63
    const int lc   = (tid & 3) * 4;   // 0,4,8,12

    float c[4][4][4];
#pragma unroll
    for (int i = 0; i < 4; i++)
#pragma unroll
        for (int j = 0; j < 4; j++)
#pragma unroll
            for (int k = 0; k < 4; k++) c[i][j][k] = 0.f;

    const int  ar0 = row0 + lr, ar1 = row0 + lr + 64;
    const bool ok0 = (ar0 < M), ok1 = (ar1 < M);
    const float* pa0 = A + (size_t)(ok0 ? ar0 : 0) * KF + lc;
    const float* pa1 = A + (size_t)(ok1 ? ar1 : 0) * KF + lc;
    const float* pb0 = B + (size_t)lr * KF + lc;
    const float* pb1 = B + (size_t)(lr + 64) * KF + lc;

    unsigned int sa0 = (unsigned int)__cvta_generic_to_shared(&As[0][lr * SMS + lc]);
    unsigned int sa1 = (unsigned int)__cvta_generic_to_shared(&As[0][(lr + 64) * SMS + lc]);
    unsigned int sb0 = (unsigned int)__cvta_generic_to_shared(&Bs[0][lr * SMS + lc]);
    unsigned int sb1 = (unsigned int)__cvta_generic_to_shared(&Bs[0][(lr + 64) * SMS + lc]);
    const unsigned int bufstride = 128 * SMS * 4;

    // prologue: stage tile 0 into buffer 0
    cp16(sa0, pa0, ok0); cp16(sa1, pa1, ok1);
    cp16(sb0, pb0, true); cp16(sb1, pb1, true);
    asm volatile("cp.async.commit_group;\n");

    int cur = 0;
    const int NT = KF / BK;   // 16
#pragma unroll 1
    for (int t = 0; t < NT; t++) {
        if (t + 1 < NT) {
            int kt = (t + 1) * BK;
            unsigned int o = (cur ^ 1) * bufstride;
            cp16(sa0 + o, pa0 + kt, ok0); cp16(sa1 + o, pa1 + kt, ok1);
            cp16(sb0 + o, pb0 + kt, true); cp16(sb1 + o, pb1 + kt, true);
            asm volatile("cp.async.commit_group;\n");
            asm volatile("cp.async.wait_group 1;\n");
        } else {
            asm volatile("cp.async.wait_group 0;\n");
        }
        __syncthreads();

        const float* Ab = &As[cur][0];
        const float* Bb = &Bs[cur][0];
#pragma unroll
        for (int k8 = 0; k8 < BK; k8 += 8) {
            unsigned a[4][4], b[4][2];
#pragma unroll
            for (int mt = 0; mt < 4; mt++) {
                int mb = warp_m * 64 + mt * 16;
                a[mt][0] = f2tf32(Ab[(mb + g)     * SMS + k8 + tg]);
                a[mt][1] = f2tf32(Ab[(mb + g + 8) * SMS + k8 + tg]);
                a[mt][2] = f2tf32(Ab[(mb + g)     * SMS + k8 + tg + 4]);
                a[mt][3] = f2tf32(Ab[(mb + g + 8) * SMS + k8 + tg + 4]);
            }
#pragma unroll
            for (int nt = 0; nt < 4; nt++) {
                int nb = warp_n * 32 + nt * 8;
                b[nt][0] = f2tf32(Bb[(nb + g) * SMS + k8 + tg]);
                b[nt][1] = f2tf32(Bb[(nb + g) * SMS + k8 + tg + 4]);
            }
#pragma unroll
            for (int mt = 0; mt < 4; mt++)
#pragma unroll
                for (int nt = 0; nt < 4; nt++) {
                    asm volatile(
                        "mma.sync.aligned.m16n8k8.row.col.f32.tf32.tf32.f32 "
                        "{%0,%1,%2,%3}, {%4,%5,%6,%7}, {%8,%9}, {%0,%1,%2,%3};\n"
                        : "+f"(c[mt][nt][0]), "+f"(c[mt][nt][1]),
                          "+f"(c[mt][nt][2]), "+f"(c[mt][nt][3])
                        : "r"(a[mt][0]), "r"(a[mt][1]), "r"(a[mt][2]), "r"(a[mt][3]),
                          "r"(b[nt][0]), "r"(b[nt][1]));
                }
        }
        __syncthreads();
        cur ^= 1;
    }

    // ---- attn weights for this thread's 8 columns (within head warp_n) ----
    float wl[4][2], wr[4][2];
#pragma unroll
    for (int nt = 0; nt < 4; nt++) {
        int col = warp_n * 32 + nt * 8 + 2 * tg;
        wl[nt][0] = attn_l[col]; wl[nt][1] = attn_l[col + 1];
        wr[nt][0] = attn_r[col]; wr[nt][1] = attn_r[col + 1];
    }

    // ---- epilogue: fp32 ft stores + fused el/er ----
#pragma unroll
    for (int mt = 0; mt < 4; mt++) {
        int r0 = row0 + warp_m * 64 + mt * 16 + g;

        float el0 = 0.f, er0 = 0.f, el1 = 0.f, er1 = 0.f;
#pragma unroll
        for (int nt = 0; nt < 4; nt++) {
            el0 = fmaf(c[mt][nt][0], wl[nt][0], el0); el0 = fmaf(c[mt][nt][1], wl[nt][1], el0);
            er0 = fmaf(c[mt][nt][0], wr[nt][0], er0); er0 = fmaf(c[mt][nt][1], wr[nt][1], er0);
            el1 = fmaf(c[mt][nt][2], wl[nt][0], el1); el1 = fmaf(c[mt][nt][3], wl[nt][1], el1);
            er1 = fmaf(c[mt][nt][2], wr[nt][0], er1); er1 = fmaf(c[mt][nt][3], wr[nt][1], er1);
        }
        el0 += __shfl_xor_sync(0xffffffffu, el0, 1); el0 += __shfl_xor_sync(0xffffffffu, el0, 2);
        er0 += __shfl_xor_sync(0xffffffffu, er0, 1); er0 += __shfl_xor_sync(0xffffffffu, er0, 2);
        el1 += __shfl_xor_sync(0xffffffffu, el1, 1); el1 += __shfl_xor_sync(0xffffffffu, el1, 2);
        er1 += __shfl_xor_sync(0xffffffffu, er1, 1); er1 += __shfl_xor_sync(0xffffffffu, er1, 2);

#pragma unroll
        for (int nt = 0; nt < 4; nt++) {
            int col = warp_n * 32 + nt * 8 + 2 * tg;
            if (r0 < M)
                *(float2*)&g_ft[(size_t)r0 * HD + col] = make_float2(c[mt][nt][0], c[mt][nt][1]);
            if (r0 + 8 < M)
                *(float2*)&g_ft[(size_t)(r0 + 8) * HD + col] = make_float2(c[mt][nt][2], c[mt][nt][3]);
        }
        if (tg == 0) {
            if (r0 < M)     { g_el[r0 * 4 + warp_n] = el0;       g_er[r0 * 4 + warp_n] = er0; }
            if (r0 + 8 < M) { g_el[(r0 + 8) * 4 + warp_n] = el1; g_er[(r0 + 8) * 4 + warp_n] = er1; }
        }
    }
}

// ================= histogram (+ reset of sync state) =========================
__global__ void hist_kernel(const int* __restrict__ dst, int E) {
    if (blockIdx.x == 0 && threadIdx.x == 0) {
        g_arrive1 = 0; g_arrive2 = 0; g_flag1 = 0; g_flag2 = 0;
    }
    int e = blockIdx.x * blockDim.x + threadIdx.x;
    if (e < E) atomicAdd(&g_cnt[dst[e]], 1);
}

// ================= fused scan + scatter (single kernel, grid barriers) =======
__global__ __launch_bounds__(256) void scan_scatter_kernel(const int* __restrict__ src,
                                                           const int* __restrict__ dst,
                                                           int M, int E, int nblk) {
    __shared__ int sh[256];
    __shared__ int sh2[512];
    __shared__ int s_last;

    const int b = blockIdx.x, t = threadIdx.x;
    const int i = b * 256 + t;

    // ---- in-block inclusive scan of counts ----
    int v = (i < M) ? g_cnt[i] : 0;
    sh[t] = v;
    __syncthreads();
#pragma unroll
    for (int ofs = 1; ofs < 256; ofs <<= 1) {
        int u = (t >= ofs) ? sh[t - ofs] : 0;
        __syncthreads();
        sh[t] += u;
        __syncthreads();
    }
    if (t == 255) g_bsum[b] = sh[255];
    __threadfence();
    __syncthreads();

    // ---- grid barrier 1: last-arriving block scans the partials ----
    if (t == 0) {
        int tk = atomicAdd(&g_arrive1, 1);
        s_last = (tk == nblk - 1) ? 1 : 0;
    }
    __syncthreads();
    if (s_last) {
        int e0 = (t < nblk) ? g_bsum[t] : 0;
        int e1 = (t + 256 < nblk) ? g_bsum[t + 256] : 0;
        sh2[t] = e0; sh2[t + 256] = e1;
        __syncthreads();
#pragma unroll
        for (int ofs = 1; ofs < 512; ofs <<= 1) {
            int u0 = (t >= ofs) ? sh2[t - ofs] : 0;
            int u1 = (t + 256 >= ofs) ? sh2[t + 256 - ofs] : 0;
            __syncthreads();
            sh2[t] += u0; sh2[t + 256] += u1;
            __syncthreads();
        }
        g_boff[t] = sh2[t] - e0;               // exclusive
        g_boff[t + 256] = sh2[t + 256] - e1;
        __threadfence();
        __syncthreads();
        if (t == 0) g_flag1 = 1;
    } else {
        if (t == 0) { while (g_flag1 == 0) {} }
        __syncthreads();
    }
    __threadfence();

    // ---- write global offsets ----
    int prefix = g_boff[b];
    if (i < M) g_off[i + 1] = sh[t] + prefix;
    if (i == 0) g_off[0] = 0;
    __threadfence();
    __syncthreads();

    // ---- grid barrier 2: all offsets visible before scatter ----
    if (t == 0) {
        int tk = atomicAdd(&g_arrive2, 1);
        if (tk == nblk - 1) { __threadfence(); g_flag2 = 1; }
        else { while (g_flag2 == 0) {} }
    }
    __syncthreads();
    __threadfence();

    // ---- destructive scatter: pos = g_off[d]++, shifting g_off by one ----
    const int stride = nblk * 256;
    for (int e = i; e < E; e += stride) {
        int d = dst[e];
        int pos = atomicAdd(&g_off[d], 1);
        g_esrc[pos] = src[e];
    }
}

// ================= fused softmax + aggregate (warp per dst node) =============
// fp32 gathers (LDG.128) + packed f32x2 FMA: minimal instructions per edge.
#define FFMA2(acc, a2, v2) \
    asm("fma.rn.f32x2 %0, %1, %2, %0;" : "+l"(acc) : "l"(a2), "l"(v2))

__global__ __launch_bounds__(256) void aggregate_kernel(float* __restrict__ out, int N) {
    int d    = (blockIdx.x * blockDim.x + threadIdx.x) >> 5;
    int lane = threadIdx.x & 31;
    if (d >= N) return;

    int beg = (d == 0) ? 0 : g_off[d - 1];
    int end = g_off[d];
    const int h     = lane >> 3;
    const float erd = g_er[d * 4 + h];
    const float* fb = g_ft + lane * 4;

    unsigned long long acc01 = 0ull, acc23 = 0ull;   // packed {f32,f32} accumulators
    float asum = 0.f;

    auto one = [&](int p_) {
        int   s = g_esrc[p_];
        float v = g_el[s * 4 + h] + erd;
        v = fmaxf(v, 0.2f * v);
        float a = __expf(v);
        asum += a;
        unsigned long long a2;
        asm("mov.b64 %0, {%1, %1};" : "=l"(a2) : "f"(a));
        ulonglong2 r = *(const ulonglong2*)(fb + ((size_t)s << 7));
        FFMA2(acc01, a2, r.x);
        FFMA2(acc23, a2, r.y);
    };

    int p = beg;
    for (; p < end && (p & 3); ++p) one(p);          // align to int4
    for (; p + 4 <= end; p += 4) {
        int4 s4 = *(const int4*)&g_esrc[p];
        float v0 = g_el[s4.x * 4 + h] + erd;
        float v1 = g_el[s4.y * 4 + h] + erd;
        float v2 = g_el[s4.z * 4 + h] + erd;
        float v3 = g_el[s4.w * 4 + h] + erd;
        v0 = fmaxf(v0, 0.2f * v0); float a0 = __expf(v0);
        v1 = fmaxf(v1, 0.2f * v1); float a1 = __expf(v1);
        v2 = fmaxf(v2, 0.2f * v2); float a2f = __expf(v2);
        v3 = fmaxf(v3, 0.2f * v3); float a3 = __expf(v3);
        asum += (a0 + a1) + (a2f + a3);
        ulonglong2 r0 = *(const ulonglong2*)(fb + ((size_t)s4.x << 7));
        ulonglong2 r1 = *(const ulonglong2*)(fb + ((size_t)s4.y << 7));
        ulonglong2 r2 = *(const ulonglong2*)(fb + ((size_t)s4.z << 7));
        ulonglong2 r3 = *(const ulonglong2*)(fb + ((size_t)s4.w << 7));
        unsigned long long p0, p1, p2, p3;
        asm("mov.b64 %0, {%1, %1};" : "=l"(p0) : "f"(a0));
        asm("mov.b64 %0, {%1, %1};" : "=l"(p1) : "f"(a1));
        asm("mov.b64 %0, {%1, %1};" : "=l"(p2) : "f"(a2f));
        asm("mov.b64 %0, {%1, %1};" : "=l"(p3) : "f"(a3));
        FFMA2(acc01, p0, r0.x); FFMA2(acc23, p0, r0.y);
        FFMA2(acc01, p1, r1.x); FFMA2(acc23, p1, r1.y);
        FFMA2(acc01, p2, r2.x); FFMA2(acc23, p2, r2.y);
        FFMA2(acc01, p3, r3.x); FFMA2(acc23, p3, r3.y);
    }
    for (; p < end; ++p) one(p);

    float inv = (asum > 0.f) ? (1.f / asum) : 0.f;
    float x0, x1, x2, x3;
    asm("mov.b64 {%0, %1}, %2;" : "=f"(x0), "=f"(x1) : "l"(acc01));
    asm("mov.b64 {%0, %1}, %2;" : "=f"(x2), "=f"(x3) : "l"(acc23));
    float4 o = make_float4(x0 * inv, x1 * inv, x2 * inv, x3 * inv);
    *(float4*)&out[(size_t)d * HD + lane * 4] = o;
}

// ================= launch ====================================================
extern "C" void kernel_launch(void* const* d_in, const int* in_sizes, int n_in,
                              void* d_out, int out_size) {
    const float* feat   = (const float*)d_in[0];
    const float* fc_w   = (const float*)d_in[1];
    const float* attn_l = (const float*)d_in[2];
    const float* attn_r = (const float*)d_in[3];
    const int*   src    = (const int*)d_in[4];
    const int*   dst    = (const int*)d_in[5];
    float*       out    = (float*)d_out;

    int M = in_sizes[0] / KF;   // nodes
    int E = in_sizes[4];        // edges
    int nblk = (M + 255) / 256;

    void* cnt_ptr = nullptr;
    cudaGetSymbolAddress(&cnt_ptr, g_cnt);
    cudaMemsetAsync(cnt_ptr, 0, (size_t)M * sizeof(int), 0);

    // projection (tf32 MMA, cp.async pipelined) + fused logits + fp32 ft
    mma_gemm_kernel<<<(M + 127) / 128, 256>>>(feat, fc_w, attn_l, attn_r, M);

    // CSR build: histogram, then fused scan+scatter (grid-barrier kernel)
    hist_kernel<<<(E + 255) / 256, 256>>>(dst, E);
    scan_scatter_kernel<<<nblk, 256>>>(src, dst, M, E, nblk);

    // fused softmax + aggregation, one warp per dst node
    aggregate_kernel<<<(M * 32 + 255) / 256, 256>>>(out, M);
}

// round 9
// speedup vs baseline: 1.7214x; 1.0728x over previous
#include <cuda_runtime.h>
#include <cuda_fp16.h>
#include <cstdint>

#define NMAX 100000
#define EMAXN 1600000
#define KF 256
#define HD 128

// ---------------- scratch (device globals; no allocs allowed) ----------------
__device__ float g_ft[(size_t)NMAX * HD];   // projected features fp32 [N,128]
__device__ float g_el[NMAX * 4];            // left logits  [N,4]
__device__ float g_er[NMAX * 4];            // right logits [N,4]
__device__ int   g_cnt[NMAX];               // histogram
__device__ int   g_off[NMAX + 1];           // CSR offsets (destructively shifted by scatter)
__device__ int   g_bsum[512];               // block partial sums
__device__ int   g_boff[512];               // block exclusive prefixes
__device__ int   g_esrc[EMAXN];             // src ids bucketed by dst
__device__ int            g_arrive1, g_arrive2;
__device__ volatile int   g_flag1, g_flag2;

// ================= tf32 tensor-core GEMM (cp.async double-buffered) ==========
// ft = feat[M,256] @ fc_w[128,256]^T ; fused el/er ; fp32 ft output.
// Block tile 128x128, BK=16, 2-stage pipeline, 8 warps (2m x 4n), warp 64x32.
#define BK   16
#define SMS  20   // 16 + 4 pad floats per row

__device__ __forceinline__ unsigned f2tf32(float f) {
    unsigned r;
    asm("cvt.rna.tf32.f32 %0, %1;" : "=r"(r) : "f"(f));
    return r;
}

__device__ __forceinline__ void cp16(unsigned int s, const float* g, bool pred) {
    int sz = pred ? 16 : 0;
    asm volatile("cp.async.ca.shared.global [%0], [%1], 16, %2;\n"
                 :: "r"(s), "l"(g), "r"(sz));
}

__global__ __launch_bounds__(256) void mma_gemm_kernel(const float* __restrict__ A,
                                                       const float* __restrict__ B,
                                                       const float* __restrict__ attn_l,
                                                       const float* __restrict__ attn_r,
                                                       int M) {
    __shared__ float As[2][128 * SMS];
    __shared__ float Bs[2][128 * SMS];

    const int tid    = threadIdx.x;
    const int wid    = tid >> 5;
    const int lane   = tid & 31;
    const int warp_m = wid >> 2;      // 0..1
    const int warp_n = wid & 3;       // 0..3 (head)
    const int g      = lane >> 2;     // 0..7
    const int tg     = lane & 3;      // 0..3

    const int row0 = blockIdx.x * 128;
    const int lr   = tid >> 2;        // 0..63
    const int lc   = (tid & 3) * 4;   // 0,4,8,12

    float c[4][4][4];
#pragma unroll
    for (int i = 0; i < 4; i++)
#pragma unroll
        for (int j = 0; j < 4; j++)
#pragma unroll
            for (int k = 0; k < 4; k++) c[i][j][k] = 0.f;

    const int  ar0 = row0 + lr, ar1 = row0 + lr + 64;
    const bool ok0 = (ar0 < M), ok1 = (ar1 < M);
    const float* pa0 = A + (size_t)(ok0 ? ar0 : 0) * KF + lc;
    const float* pa1 = A + (size_t)(ok1 ? ar1 : 0) * KF + lc;
    const float* pb0 = B + (size_t)lr * KF + lc;
    const float* pb1 = B + (size_t)(lr + 64) * KF + lc;

    unsigned int sa0 = (unsigned int)__cvta_generic_to_shared(&As[0][lr * SMS + lc]);
    unsigned int sa1 = (unsigned int)__cvta_generic_to_shared(&As[0][(lr + 64) * SMS + lc]);
    unsigned int sb0 = (unsigned int)__cvta_generic_to_shared(&Bs[0][lr * SMS + lc]);
    unsigned int sb1 = (unsigned int)__cvta_generic_to_shared(&Bs[0][(lr + 64) * SMS + lc]);
    const unsigned int bufstride = 128 * SMS * 4;

    // prologue: stage tile 0 into buffer 0
    cp16(sa0, pa0, ok0); cp16(sa1, pa1, ok1);
    cp16(sb0, pb0, true); cp16(sb1, pb1, true);
    asm volatile("cp.async.commit_group;\n");

    int cur = 0;
    const int NT = KF / BK;   // 16
#pragma unroll 1
    for (int t = 0; t < NT; t++) {
        if (t + 1 < NT) {
            int kt = (t + 1) * BK;
            unsigned int o = (cur ^ 1) * bufstride;
            cp16(sa0 + o, pa0 + kt, ok0); cp16(sa1 + o, pa1 + kt, ok1);
            cp16(sb0 + o, pb0 + kt, true); cp16(sb1 + o, pb1 + kt, true);
            asm volatile("cp.async.commit_group;\n");
            asm volatile("cp.async.wait_group 1;\n");
        } else {
            asm volatile("cp.async.wait_group 0;\n");
        }
        __syncthreads();

        const float* Ab = &As[cur][0];
        const float* Bb = &Bs[cur][0];
#pragma unroll
        for (int k8 = 0; k8 < BK; k8 += 8) {
            unsigned a[4][4], b[4][2];
#pragma unroll
            for (int mt = 0; mt < 4; mt++) {
                int mb = warp_m * 64 + mt * 16;
                a[mt][0] = f2tf32(Ab[(mb + g)     * SMS + k8 + tg]);
                a[mt][1] = f2tf32(Ab[(mb + g + 8) * SMS + k8 + tg]);
                a[mt][2] = f2tf32(Ab[(mb + g)     * SMS + k8 + tg + 4]);
                a[mt][3] = f2tf32(Ab[(mb + g + 8) * SMS + k8 + tg + 4]);
            }
#pragma unroll
            for (int nt = 0; nt < 4; nt++) {
                int nb = warp_n * 32 + nt * 8;
                b[nt][0] = f2tf32(Bb[(nb + g) * SMS + k8 + tg]);
                b[nt][1] = f2tf32(Bb[(nb + g) * SMS + k8 + tg + 4]);
            }
#pragma unroll
            for (int mt = 0; mt < 4; mt++)
#pragma unroll
                for (int nt = 0; nt < 4; nt++) {
                    asm volatile(
                        "mma.sync.aligned.m16n8k8.row.col.f32.tf32.tf32.f32 "
                        "{%0,%1,%2,%3}, {%4,%5,%6,%7}, {%8,%9}, {%0,%1,%2,%3};\n"
                        : "+f"(c[mt][nt][0]), "+f"(c[mt][nt][1]),
                          "+f"(c[mt][nt][2]), "+f"(c[mt][nt][3])
                        : "r"(a[mt][0]), "r"(a[mt][1]), "r"(a[mt][2]), "r"(a[mt][3]),
                          "r"(b[nt][0]), "r"(b[nt][1]));
                }
        }
        __syncthreads();
        cur ^= 1;
    }

    // ---- attn weights for this thread's 8 columns (within head warp_n) ----
    float wl[4][2], wr[4][2];
#pragma unroll
    for (int nt = 0; nt < 4; nt++) {
        int col = warp_n * 32 + nt * 8 + 2 * tg;
        wl[nt][0] = attn_l[col]; wl[nt][1] = attn_l[col + 1];
        wr[nt][0] = attn_r[col]; wr[nt][1] = attn_r[col + 1];
    }

    // ---- epilogue: fp32 ft stores + fused el/er ----
#pragma unroll
    for (int mt = 0; mt < 4; mt++) {
        int r0 = row0 + warp_m * 64 + mt * 16 + g;

        float el0 = 0.f, er0 = 0.f, el1 = 0.f, er1 = 0.f;
#pragma unroll
        for (int nt = 0; nt < 4; nt++) {
            el0 = fmaf(c[mt][nt][0], wl[nt][0], el0); el0 = fmaf(c[mt][nt][1], wl[nt][1], el0);
            er0 = fmaf(c[mt][nt][0], wr[nt][0], er0); er0 = fmaf(c[mt][nt][1], wr[nt][1], er0);
            el1 = fmaf(c[mt][nt][2], wl[nt][0], el1); el1 = fmaf(c[mt][nt][3], wl[nt][1], el1);
            er1 = fmaf(c[mt][nt][2], wr[nt][0], er1); er1 = fmaf(c[mt][nt][3], wr[nt][1], er1);
        }
        el0 += __shfl_xor_sync(0xffffffffu, el0, 1); el0 += __shfl_xor_sync(0xffffffffu, el0, 2);
        er0 += __shfl_xor_sync(0xffffffffu, er0, 1); er0 += __shfl_xor_sync(0xffffffffu, er0, 2);
        el1 += __shfl_xor_sync(0xffffffffu, el1, 1); el1 += __shfl_xor_sync(0xffffffffu, el1, 2);
        er1 += __shfl_xor_sync(0xffffffffu, er1, 1); er1 += __shfl_xor_sync(0xffffffffu, er1, 2);

#pragma unroll
        for (int nt = 0; nt < 4; nt++) {
            int col = warp_n * 32 + nt * 8 + 2 * tg;
            if (r0 < M)
                *(float2*)&g_ft[(size_t)r0 * HD + col] = make_float2(c[mt][nt][0], c[mt][nt][1]);
            if (r0 + 8 < M)
                *(float2*)&g_ft[(size_t)(r0 + 8) * HD + col] = make_float2(c[mt][nt][2], c[mt][nt][3]);
        }
        if (tg == 0) {
            if (r0 < M)     { g_el[r0 * 4 + warp_n] = el0;       g_er[r0 * 4 + warp_n] = er0; }
            if (r0 + 8 < M) { g_el[(r0 + 8) * 4 + warp_n] = el1; g_er[(r0 + 8) * 4 + warp_n] = er1; }
        }
    }
}

// ================= histogram (+ reset of sync state) =========================
__global__ void hist_kernel(const int* __restrict__ dst, int E) {
    if (blockIdx.x == 0 && threadIdx.x == 0) {
        g_arrive1 = 0; g_arrive2 = 0; g_flag1 = 0; g_flag2 = 0;
    }
    int e = blockIdx.x * blockDim.x + threadIdx.x;
    if (e < E) atomicAdd(&g_cnt[dst[e]], 1);
}

// ================= fused scan + scatter (single kernel, grid barriers) =======
__global__ __launch_bounds__(256) void scan_scatter_kernel(const int* __restrict__ src,
                                                           const int* __restrict__ dst,
                                                           int M, int E, int nblk) {
    __shared__ int sh[256];
    __shared__ int sh2[512];
    __shared__ int s_last;

    const int b = blockIdx.x, t = threadIdx.x;
    const int i = b * 256 + t;

    // ---- in-block inclusive scan of counts ----
    int v = (i < M) ? g_cnt[i] : 0;
    sh[t] = v;
    __syncthreads();
#pragma unroll
    for (int ofs = 1; ofs < 256; ofs <<= 1) {
        int u = (t >= ofs) ? sh[t - ofs] : 0;
        __syncthreads();
        sh[t] += u;
        __syncthreads();
    }
    if (t == 255) g_bsum[b] = sh[255];
    __threadfence();
    __syncthreads();

    // ---- grid barrier 1: last-arriving block scans the partials ----
    if (t == 0) {
        int tk = atomicAdd(&g_arrive1, 1);
        s_last = (tk == nblk - 1) ? 1 : 0;
    }
    __syncthreads();
    if (s_last) {
        int e0 = (t < nblk) ? g_bsum[t] : 0;
        int e1 = (t + 256 < nblk) ? g_bsum[t + 256] : 0;
        sh2[t] = e0; sh2[t + 256] = e1;
        __syncthreads();
#pragma unroll
        for (int ofs = 1; ofs < 512; ofs <<= 1) {
            int u0 = (t >= ofs) ? sh2[t - ofs] : 0;
            int u1 = (t + 256 >= ofs) ? sh2[t + 256 - ofs] : 0;
            __syncthreads();
            sh2[t] += u0; sh2[t + 256] += u1;
            __syncthreads();
        }
        g_boff[t] = sh2[t] - e0;               // exclusive
        g_boff[t + 256] = sh2[t + 256] - e1;
        __threadfence();
        __syncthreads();
        if (t == 0) g_flag1 = 1;
    } else {
        if (t == 0) { while (g_flag1 == 0) {} }
        __syncthreads();
    }
    __threadfence();

    // ---- write global offsets ----
    int prefix = g_boff[b];
    if (i < M) g_off[i + 1] = sh[t] + prefix;
    if (i == 0) g_off[0] = 0;
    __threadfence();
    __syncthreads();

    // ---- grid barrier 2: all offsets visible before scatter ----
    if (t == 0) {
        int tk = atomicAdd(&g_arrive2, 1);
        if (tk == nblk - 1) { __threadfence(); g_flag2 = 1; }
        else { while (g_flag2 == 0) {} }
    }
    __syncthreads();
    __threadfence();

    // ---- destructive scatter: pos = g_off[d]++, shifting g_off by one ----
    const int stride = nblk * 256;
    for (int e = i; e < E; e += stride) {
        int d = dst[e];
        int pos = atomicAdd(&g_off[d], 1);
        g_esrc[pos] = src[e];
    }
}

// ================= fused softmax + aggregate (warp per dst node) =============
// fp32 gathers (LDG.128) + packed f32x2 FMA: minimal instructions per edge.
#define FFMA2(acc, a2, v2) \
    asm("fma.rn.f32x2 %0, %1, %2, %0;" : "+l"(acc) : "l"(a2), "l"(v2))

__global__ __launch_bounds__(256) void aggregate_kernel(float* __restrict__ out, int N) {
    int d    = (blockIdx.x * blockDim.x + threadIdx.x) >> 5;
    int lane = threadIdx.x & 31;
    if (d >= N) return;

    int beg = (d == 0) ? 0 : g_off[d - 1];
    int end = g_off[d];
    const int h     = lane >> 3;
    const float erd = g_er[d * 4 + h];
    const float* fb = g_ft + lane * 4;

    unsigned long long acc01 = 0ull, acc23 = 0ull;   // packed {f32,f32} accumulators
    float asum = 0.f;

    auto one = [&](int p_) {
        int   s = g_esrc[p_];
        float v = g_el[s * 4 + h] + erd;
        v = fmaxf(v, 0.2f * v);
        float a = __expf(v);
        asum += a;
        unsigned long long a2;
        asm("mov.b64 %0, {%1, %1};" : "=l"(a2) : "f"(a));
        ulonglong2 r = *(const ulonglong2*)(fb + ((size_t)s << 7));
        FFMA2(acc01, a2, r.x);
        FFMA2(acc23, a2, r.y);
    };

    int p = beg;
    for (; p < end && (p & 3); ++p) one(p);          // align to int4
    for (; p + 4 <= end; p += 4) {
        int4 s4 = *(const int4*)&g_esrc[p];
        float v0 = g_el[s4.x * 4 + h] + erd;
        float v1 = g_el[s4.y * 4 + h] + erd;
        float v2 = g_el[s4.z * 4 + h] + erd;
        float v3 = g_el[s4.w * 4 + h] + erd;
        v0 = fmaxf(v0, 0.2f * v0); float a0 = __expf(v0);
        v1 = fmaxf(v1, 0.2f * v1); float a1 = __expf(v1);
        v2 = fmaxf(v2, 0.2f * v2); float a2f = __expf(v2);
        v3 = fmaxf(v3, 0.2f * v3); float a3 = __expf(v3);
        asum += (a0 + a1) + (a2f + a3);
        ulonglong2 r0 = *(const ulonglong2*)(fb + ((size_t)s4.x << 7));
        ulonglong2 r1 = *(const ulonglong2*)(fb + ((size_t)s4.y << 7));
        ulonglong2 r2 = *(const ulonglong2*)(fb + ((size_t)s4.z << 7));
        ulonglong2 r3 = *(const ulonglong2*)(fb + ((size_t)s4.w << 7));
        unsigned long long p0, p1, p2, p3;
        asm("mov.b64 %0, {%1, %1};" : "=l"(p0) : "f"(a0));
        asm("mov.b64 %0, {%1, %1};" : "=l"(p1) : "f"(a1));
        asm("mov.b64 %0, {%1, %1};" : "=l"(p2) : "f"(a2f));
        asm("mov.b64 %0, {%1, %1};" : "=l"(p3) : "f"(a3));
        FFMA2(acc01, p0, r0.x); FFMA2(acc23, p0, r0.y);
        FFMA2(acc01, p1, r1.x); FFMA2(acc23, p1, r1.y);
        FFMA2(acc01, p2, r2.x); FFMA2(acc23, p2, r2.y);
        FFMA2(acc01, p3, r3.x); FFMA2(acc23, p3, r3.y);
    }
    for (; p < end; ++p) one(p);

    float inv = (asum > 0.f) ? (1.f / asum) : 0.f;
    float x0, x1, x2, x3;
    asm("mov.b64 {%0, %1}, %2;" : "=f"(x0), "=f"(x1) : "l"(acc01));
    asm("mov.b64 {%0, %1}, %2;" : "=f"(x2), "=f"(x3) : "l"(acc23));
    float4 o = make_float4(x0 * inv, x1 * inv, x2 * inv, x3 * inv);
    *(float4*)&out[(size_t)d * HD + lane * 4] = o;
}

// ================= launch ====================================================
// GEMM branch (stream s1) runs concurrently with the CSR branch (main stream);
// they touch disjoint data and join before the aggregate.
extern "C" void kernel_launch(void* const* d_in, const int* in_sizes, int n_in,
                              void* d_out, int out_size) {
    const float* feat   = (const float*)d_in[0];
    const float* fc_w   = (const float*)d_in[1];
    const float* attn_l = (const float*)d_in[2];
    const float* attn_r = (const float*)d_in[3];
    const int*   src    = (const int*)d_in[4];
    const int*   dst    = (const int*)d_in[5];
    float*       out    = (float*)d_out;

    int M = in_sizes[0] / KF;   // nodes
    int E = in_sizes[4];        // edges
    int nblk = (M + 255) / 256;

    void* cnt_ptr = nullptr;
    cudaGetSymbolAddress(&cnt_ptr, g_cnt);

    cudaStream_t s1;
    cudaEvent_t  ev_fork, ev_join;
    cudaStreamCreateWithFlags(&s1, cudaStreamNonBlocking);
    cudaEventCreateWithFlags(&ev_fork, cudaEventDisableTiming);
    cudaEventCreateWithFlags(&ev_join, cudaEventDisableTiming);

    // ---- fork: GEMM branch on s1 ----
    cudaEventRecord(ev_fork, 0);
    cudaStreamWaitEvent(s1, ev_fork, 0);
    mma_gemm_kernel<<<(M + 127) / 128, 256, 0, s1>>>(feat, fc_w, attn_l, attn_r, M);
    cudaEventRecord(ev_join, s1);

    // ---- CSR branch on main stream ----
    cudaMemsetAsync(cnt_ptr, 0, (size_t)M * sizeof(int), 0);
    hist_kernel<<<(E + 255) / 256, 256>>>(dst, E);
    scan_scatter_kernel<<<nblk, 256>>>(src, dst, M, E, nblk);

    // ---- join, then aggregate ----
    cudaStreamWaitEvent(0, ev_join, 0);
    aggregate_kernel<<<(M * 32 + 255) / 256, 256>>>(out, M);
}